// round 4
// baseline (speedup 1.0000x reference)
#include <cuda_runtime.h>

#define NWIN  64
#define NHEAD 12
#define LTOK  343
#define HEADD 32
#define DIMM  384
#define TBLN  2197
#define QSCALE 0.17677669529663687f   // 32^-0.5
#define MROWS (NWIN*LTOK)             // 21952

// -------- scratch (static device globals; no runtime allocation) --------
__device__ __align__(16) float g_q[(size_t)NWIN*NHEAD*LTOK*HEADD];
__device__ __align__(16) float g_k[(size_t)NWIN*NHEAD*LTOK*HEADD];
__device__ __align__(16) float g_v[(size_t)NWIN*NHEAD*LTOK*HEADD];
__device__ __align__(16) float g_ao[(size_t)MROWS*DIMM];
__device__ int g_mask_mode;   // 0 = 1-byte elements, 1 = 4-byte elements

// ======================================================================
// Detect mask storage dtype by scanning first 4096 words.
//  - all words in {0,1}            -> int32 bools  -> mode 1
//  - all words in {0,0x3F800000}   -> float32 bools-> mode 1
//  - otherwise                     -> packed bytes -> mode 0
// Deterministic for fixed input.
// ======================================================================
__global__ void detect_mask_kernel(const unsigned int* __restrict__ m)
{
    __shared__ int s_not01, s_notf;
    if (threadIdx.x == 0) { s_not01 = 0; s_notf = 0; }
    __syncthreads();
    int bad01 = 0, badf = 0;
    for (int i = threadIdx.x; i < 4096; i += 256) {
        unsigned int w = m[i];
        if (w > 1u) bad01 = 1;
        if (w != 0u && w != 0x3F800000u) badf = 1;
    }
    if (bad01) atomicOr(&s_not01, 1);
    if (badf)  atomicOr(&s_notf, 1);
    __syncthreads();
    if (threadIdx.x == 0)
        g_mask_mode = (!s_not01 || !s_notf) ? 1 : 0;
}

// ======================================================================
// QKV GEMM: [21952 x 384] @ [384 x 1152], scatter epilogue into
// g_q/g_k/g_v laid out [n][h][l][c].
// ======================================================================
__global__ __launch_bounds__(256)
void qkv_gemm_kernel(const float* __restrict__ A, const float* __restrict__ B)
{
    __shared__ float As[16][132];
    __shared__ float Bs[16][132];

    const int M = MROWS, N = 3 * DIMM, K = DIMM;
    const int bm  = blockIdx.x * 128;
    const int bn  = blockIdx.y * 128;
    const int tid = threadIdx.x;
    const int tx  = tid & 15;
    const int ty  = tid >> 4;

    float acc[8][8];
    #pragma unroll
    for (int i = 0; i < 8; i++)
        #pragma unroll
        for (int j = 0; j < 8; j++) acc[i][j] = 0.f;

    for (int k0 = 0; k0 < K; k0 += 16) {
        #pragma unroll
        for (int i = 0; i < 2; i++) {
            int t   = tid + i * 256;
            int row = t >> 2;
            int c4  = (t & 3) << 2;
            int gr  = bm + row;
            float4 av = make_float4(0.f, 0.f, 0.f, 0.f);
            if (gr < M) av = *(const float4*)(A + (size_t)gr * K + k0 + c4);
            As[c4 + 0][row] = av.x;
            As[c4 + 1][row] = av.y;
            As[c4 + 2][row] = av.z;
            As[c4 + 3][row] = av.w;
        }
        #pragma unroll
        for (int i = 0; i < 2; i++) {
            int t   = tid + i * 256;
            int row = t >> 5;
            int c4  = (t & 31) << 2;
            *(float4*)&Bs[row][c4] =
                *(const float4*)(B + (size_t)(k0 + row) * N + bn + c4);
        }
        __syncthreads();

        #pragma unroll
        for (int kk = 0; kk < 16; kk++) {
            float ra[8], rb[8];
            *(float4*)&ra[0] = *(const float4*)&As[kk][ty * 8];
            *(float4*)&ra[4] = *(const float4*)&As[kk][ty * 8 + 4];
            *(float4*)&rb[0] = *(const float4*)&Bs[kk][tx * 8];
            *(float4*)&rb[4] = *(const float4*)&Bs[kk][tx * 8 + 4];
            #pragma unroll
            for (int i = 0; i < 8; i++)
                #pragma unroll
                for (int j = 0; j < 8; j++)
                    acc[i][j] = fmaf(ra[i], rb[j], acc[i][j]);
        }
        __syncthreads();
    }

    #pragma unroll
    for (int i = 0; i < 8; i++) {
        int gr = bm + ty * 8 + i;
        if (gr >= M) continue;
        int n = gr / LTOK;
        int l = gr - n * LTOK;
        #pragma unroll
        for (int j = 0; j < 8; j++) {
            int col = bn + tx * 8 + j;
            int s   = col / DIMM;
            int rem = col - s * DIMM;
            int h   = rem >> 5;
            int c   = rem & 31;
            float* dst = (s == 0) ? g_q : ((s == 1) ? g_k : g_v);
            dst[(((size_t)(n * NHEAD + h)) * LTOK + l) * HEADD + c] = acc[i][j];
        }
    }
}

// ======================================================================
// Output projection: g_ao [21952 x 384] @ [384 x 384] + bias -> d_out
// ======================================================================
__global__ __launch_bounds__(256)
void proj_gemm_kernel(const float* __restrict__ B,
                      const float* __restrict__ bias,
                      float* __restrict__ C)
{
    __shared__ float As[16][132];
    __shared__ float Bs[16][132];

    const int M = MROWS, N = DIMM, K = DIMM;
    const int bm  = blockIdx.x * 128;
    const int bn  = blockIdx.y * 128;
    const int tid = threadIdx.x;
    const int tx  = tid & 15;
    const int ty  = tid >> 4;

    float acc[8][8];
    #pragma unroll
    for (int i = 0; i < 8; i++)
        #pragma unroll
        for (int j = 0; j < 8; j++) acc[i][j] = 0.f;

    for (int k0 = 0; k0 < K; k0 += 16) {
        #pragma unroll
        for (int i = 0; i < 2; i++) {
            int t   = tid + i * 256;
            int row = t >> 2;
            int c4  = (t & 3) << 2;
            int gr  = bm + row;
            float4 av = make_float4(0.f, 0.f, 0.f, 0.f);
            if (gr < M) av = *(const float4*)(g_ao + (size_t)gr * K + k0 + c4);
            As[c4 + 0][row] = av.x;
            As[c4 + 1][row] = av.y;
            As[c4 + 2][row] = av.z;
            As[c4 + 3][row] = av.w;
        }
        #pragma unroll
        for (int i = 0; i < 2; i++) {
            int t   = tid + i * 256;
            int row = t >> 5;
            int c4  = (t & 31) << 2;
            *(float4*)&Bs[row][c4] =
                *(const float4*)(B + (size_t)(k0 + row) * N + bn + c4);
        }
        __syncthreads();

        #pragma unroll
        for (int kk = 0; kk < 16; kk++) {
            float ra[8], rb[8];
            *(float4*)&ra[0] = *(const float4*)&As[kk][ty * 8];
            *(float4*)&ra[4] = *(const float4*)&As[kk][ty * 8 + 4];
            *(float4*)&rb[0] = *(const float4*)&Bs[kk][tx * 8];
            *(float4*)&rb[4] = *(const float4*)&Bs[kk][tx * 8 + 4];
            #pragma unroll
            for (int i = 0; i < 8; i++)
                #pragma unroll
                for (int j = 0; j < 8; j++)
                    acc[i][j] = fmaf(ra[i], rb[j], acc[i][j]);
        }
        __syncthreads();
    }

    #pragma unroll
    for (int i = 0; i < 8; i++) {
        int gr = bm + ty * 8 + i;
        if (gr >= M) continue;
        int col0 = bn + tx * 8;
        float4 b0 = *(const float4*)&bias[col0];
        float4 b1 = *(const float4*)&bias[col0 + 4];
        float4 o0 = make_float4(acc[i][0] + b0.x, acc[i][1] + b0.y,
                                acc[i][2] + b0.z, acc[i][3] + b0.w);
        float4 o1 = make_float4(acc[i][4] + b1.x, acc[i][5] + b1.y,
                                acc[i][6] + b1.z, acc[i][7] + b1.w);
        float* crow = C + (size_t)gr * N + col0;
        *(float4*)crow       = o0;
        *(float4*)(crow + 4) = o1;
    }
}

// ======================================================================
// Fused window attention: one block per (window, head).
// ======================================================================
__global__ __launch_bounds__(256)
void attn_kernel(const float* __restrict__ table,
                 const int* __restrict__ rel_idx,
                 const void* __restrict__ mask)
{
    extern __shared__ float sm[];
    float* Ks = sm;                       // [343][36]
    float* Vs = Ks + LTOK * 36;           // [343][36]
    float* Qs = Vs + LTOK * 36;           // [64][36]
    float* Ss = Qs + 64 * 36;             // [64][344]
    float* Tb = Ss + 64 * 344;            // [2197]

    const int tid = threadIdx.x;
    const int bh  = blockIdx.x;
    const int n   = bh / NHEAD;
    const int h   = bh - n * NHEAD;

    const int mmode = g_mask_mode;        // uniform per launch
    const unsigned char* mb8 =
        (const unsigned char*)mask + (size_t)n * LTOK * LTOK;
    const unsigned int* mb32 =
        (const unsigned int*)mask + (size_t)n * LTOK * LTOK;

    for (int i = tid; i < TBLN; i += 256)
        Tb[i] = table[(size_t)i * NHEAD + h];

    const float* kg = g_k + (size_t)bh * LTOK * HEADD;
    const float* vg = g_v + (size_t)bh * LTOK * HEADD;
    for (int i = tid; i < LTOK * 8; i += 256) {
        int row = i >> 3, c4 = (i & 7) << 2;
        *(float4*)&Ks[row * 36 + c4] = *(const float4*)(kg + (size_t)i * 4);
        *(float4*)&Vs[row * 36 + c4] = *(const float4*)(vg + (size_t)i * 4);
    }
    __syncthreads();

    const float* qg = g_q + (size_t)bh * LTOK * HEADD;

    for (int q0 = 0; q0 < LTOK; q0 += 64) {
        const int qn = min(64, LTOK - q0);

        for (int i = tid; i < qn * 8; i += 256) {
            int row = i >> 3, c4 = (i & 7) << 2;
            *(float4*)&Qs[row * 36 + c4] =
                *(const float4*)(qg + (size_t)q0 * HEADD + (size_t)i * 4);
        }
        __syncthreads();

        const int ngroups = (qn + 3) >> 2;
        for (int idx = tid; idx < ngroups * LTOK; idx += 256) {
            int g   = idx / LTOK;
            int kj  = idx - g * LTOK;
            int qb4 = g << 2;
            float a0 = 0.f, a1 = 0.f, a2 = 0.f, a3 = 0.f;
            const float* krow = Ks + kj * 36;
            const float* r0 = Qs + (qb4 + 0) * 36;
            const float* r1 = Qs + (qb4 + 1) * 36;
            const float* r2 = Qs + (qb4 + 2) * 36;
            const float* r3 = Qs + (qb4 + 3) * 36;
            #pragma unroll
            for (int cc = 0; cc < 8; cc++) {
                float4 kv  = *(const float4*)(krow + cc * 4);
                float4 qa  = *(const float4*)(r0 + cc * 4);
                float4 qv1 = *(const float4*)(r1 + cc * 4);
                float4 qv2 = *(const float4*)(r2 + cc * 4);
                float4 qv3 = *(const float4*)(r3 + cc * 4);
                a0 += qa.x * kv.x + qa.y * kv.y + qa.z * kv.z + qa.w * kv.w;
                a1 += qv1.x * kv.x + qv1.y * kv.y + qv1.z * kv.z + qv1.w * kv.w;
                a2 += qv2.x * kv.x + qv2.y * kv.y + qv2.z * kv.z + qv2.w * kv.w;
                a3 += qv3.x * kv.x + qv3.y * kv.y + qv3.z * kv.z + qv3.w * kv.w;
            }
            float accs[4] = {a0, a1, a2, a3};
            #pragma unroll
            for (int u = 0; u < 4; u++) {
                int qi = qb4 + u;
                if (qi < qn) {
                    size_t off = (size_t)(q0 + qi) * LTOK + kj;
                    bool masked = mmode ? (mb32[off] != 0u) : (mb8[off] != 0);
                    float b = Tb[rel_idx[off]];
                    float sv = masked ? -1e30f : fmaf(accs[u], QSCALE, b);
                    Ss[qi * 344 + kj] = sv;
                }
            }
        }
        __syncthreads();

        const int warp = tid >> 5, lane = tid & 31;
        for (int row = warp; row < qn; row += 8) {
            float* sr = Ss + row * 344;
            float m = -1e30f;
            for (int j = lane; j < LTOK; j += 32) m = fmaxf(m, sr[j]);
            #pragma unroll
            for (int off = 16; off > 0; off >>= 1)
                m = fmaxf(m, __shfl_xor_sync(0xffffffffu, m, off));
            float ssum = 0.f;
            for (int j = lane; j < LTOK; j += 32) {
                float e = __expf(sr[j] - m);
                sr[j] = e;
                ssum += e;
            }
            #pragma unroll
            for (int off = 16; off > 0; off >>= 1)
                ssum += __shfl_xor_sync(0xffffffffu, ssum, off);
            float inv = 1.f / ssum;
            for (int j = lane; j < LTOK; j += 32) sr[j] *= inv;
        }
        __syncthreads();

        const int ntasks = ((qn + 1) >> 1) * 8;
        for (int t = tid; t < ntasks; t += 256) {
            int qg2 = t >> 3, cg = t & 7;
            int qi0 = qg2 << 1;
            const float* s0 = Ss + qi0 * 344;
            const float* s1 = s0 + 344;
            const float* vcol = Vs + cg * 4;
            float4 ac0 = make_float4(0.f, 0.f, 0.f, 0.f);
            float4 ac1 = make_float4(0.f, 0.f, 0.f, 0.f);
            #pragma unroll 4
            for (int j = 0; j < LTOK; j++) {
                float4 vv = *(const float4*)(vcol + (size_t)j * 36);
                float w0 = s0[j], w1 = s1[j];
                ac0.x = fmaf(w0, vv.x, ac0.x);
                ac0.y = fmaf(w0, vv.y, ac0.y);
                ac0.z = fmaf(w0, vv.z, ac0.z);
                ac0.w = fmaf(w0, vv.w, ac0.w);
                ac1.x = fmaf(w1, vv.x, ac1.x);
                ac1.y = fmaf(w1, vv.y, ac1.y);
                ac1.z = fmaf(w1, vv.z, ac1.z);
                ac1.w = fmaf(w1, vv.w, ac1.w);
            }
            float* og = g_ao + ((size_t)(n * LTOK + q0 + qi0)) * DIMM
                        + h * HEADD + cg * 4;
            *(float4*)og = ac0;
            if (qi0 + 1 < qn) *(float4*)(og + DIMM) = ac1;
        }
        __syncthreads();
    }
}

// ======================================================================
extern "C" void kernel_launch(void* const* d_in, const int* in_sizes, int n_in,
                              void* d_out, int out_size)
{
    const float *x = nullptr, *qkvw = nullptr, *tbl = nullptr;
    const float *pw = nullptr, *pb = nullptr;
    const void* mask = nullptr;
    const int* ridx = nullptr;
    for (int i = 0; i < n_in; i++) {
        switch (in_sizes[i]) {
            case 8429568:  x    = (const float*)d_in[i]; break;  // x (21952,384)
            case 442368:   qkvw = (const float*)d_in[i]; break;  // (384,1152)
            case 26364:    tbl  = (const float*)d_in[i]; break;  // (2197,12)
            case 147456:   pw   = (const float*)d_in[i]; break;  // (384,384)
            case 384:      pb   = (const float*)d_in[i]; break;  // (384,)
            case 7530496:  mask = d_in[i]; break;                // bool (unknown storage)
            case 117649:   ridx = (const int*)d_in[i]; break;    // (343,343)
        }
    }
    if (n_in >= 7) {
        if (!x)    x    = (const float*)d_in[0];
        if (!qkvw) qkvw = (const float*)d_in[1];
        if (!tbl)  tbl  = (const float*)d_in[2];
        if (!pw)   pw   = (const float*)d_in[3];
        if (!pb)   pb   = (const float*)d_in[4];
        if (!mask) mask = d_in[5];
        if (!ridx) ridx = (const int*)d_in[6];
    }

    // 0) detect mask storage dtype
    detect_mask_kernel<<<1, 256>>>((const unsigned int*)mask);

    // 1) QKV projection + scatter to [n][h][l][c]
    qkv_gemm_kernel<<<dim3(172, 9), 256>>>(x, qkvw);

    // 2) fused attention
    size_t smem = (size_t)(LTOK * 36 * 2 + 64 * 36 + 64 * 344 + TBLN) * sizeof(float);
    cudaFuncSetAttribute(attn_kernel,
                         cudaFuncAttributeMaxDynamicSharedMemorySize, (int)smem);
    attn_kernel<<<NWIN * NHEAD, 256, smem>>>(tbl, ridx, mask);

    // 3) output projection + bias
    proj_gemm_kernel<<<dim3(172, 3), 256>>>(pw, pb, (float*)d_out);
}

// round 5
// speedup vs baseline: 1.4646x; 1.4646x over previous
#include <cuda_runtime.h>

#define NWIN  64
#define NHEAD 12
#define LTOK  343
#define HEADD 32
#define DIMM  384
#define TBLN  2197
#define QSCALE 0.17677669529663687f   // 32^-0.5
#define MROWS (NWIN*LTOK)             // 21952

// -------- scratch (static device globals; no runtime allocation) --------
__device__ __align__(16) float g_q[(size_t)NWIN*NHEAD*LTOK*HEADD];
__device__ __align__(16) float g_k[(size_t)NWIN*NHEAD*LTOK*HEADD];
__device__ __align__(16) float g_v[(size_t)NWIN*NHEAD*LTOK*HEADD];
__device__ __align__(16) float g_ao[(size_t)MROWS*DIMM];
__device__ __align__(16) float g_bias[(size_t)NHEAD*LTOK*LTOK];   // 5.6 MB
__device__ int g_mask_mode;   // 0 = 1-byte elements, 1 = 4-byte elements

// ======================================================================
// Detect mask storage dtype by scanning first 4096 words.
// ======================================================================
__global__ void detect_mask_kernel(const unsigned int* __restrict__ m)
{
    __shared__ int s_not01, s_notf;
    if (threadIdx.x == 0) { s_not01 = 0; s_notf = 0; }
    __syncthreads();
    int bad01 = 0, badf = 0;
    for (int i = threadIdx.x; i < 4096; i += 256) {
        unsigned int w = m[i];
        if (w > 1u) bad01 = 1;
        if (w != 0u && w != 0x3F800000u) badf = 1;
    }
    if (bad01) atomicOr(&s_not01, 1);
    if (badf)  atomicOr(&s_notf, 1);
    __syncthreads();
    if (threadIdx.x == 0)
        g_mask_mode = (!s_not01 || !s_notf) ? 1 : 0;
}

// ======================================================================
// Precompute per-head bias matrix: g_bias[h][i][j] = table[rel_idx[i][j]][h]
// ======================================================================
__global__ __launch_bounds__(256)
void bias_prep_kernel(const float* __restrict__ table,
                      const int* __restrict__ rel_idx)
{
    int i = blockIdx.x * 256 + threadIdx.x;
    if (i < LTOK * LTOK) {
        int idx = rel_idx[i];
        #pragma unroll
        for (int h = 0; h < NHEAD; h++)
            g_bias[(size_t)h * LTOK * LTOK + i] = table[(size_t)idx * NHEAD + h];
    }
}

// ======================================================================
// QKV GEMM: [21952 x 384] @ [384 x 1152], scatter epilogue into
// g_q/g_k/g_v laid out [n][h][l][c].
// ======================================================================
__global__ __launch_bounds__(256)
void qkv_gemm_kernel(const float* __restrict__ A, const float* __restrict__ B)
{
    __shared__ float As[16][132];
    __shared__ float Bs[16][132];

    const int M = MROWS, N = 3 * DIMM, K = DIMM;
    const int bm  = blockIdx.x * 128;
    const int bn  = blockIdx.y * 128;
    const int tid = threadIdx.x;
    const int tx  = tid & 15;
    const int ty  = tid >> 4;

    float acc[8][8];
    #pragma unroll
    for (int i = 0; i < 8; i++)
        #pragma unroll
        for (int j = 0; j < 8; j++) acc[i][j] = 0.f;

    for (int k0 = 0; k0 < K; k0 += 16) {
        #pragma unroll
        for (int i = 0; i < 2; i++) {
            int t   = tid + i * 256;
            int row = t >> 2;
            int c4  = (t & 3) << 2;
            int gr  = bm + row;
            float4 av = make_float4(0.f, 0.f, 0.f, 0.f);
            if (gr < M) av = *(const float4*)(A + (size_t)gr * K + k0 + c4);
            As[c4 + 0][row] = av.x;
            As[c4 + 1][row] = av.y;
            As[c4 + 2][row] = av.z;
            As[c4 + 3][row] = av.w;
        }
        #pragma unroll
        for (int i = 0; i < 2; i++) {
            int t   = tid + i * 256;
            int row = t >> 5;
            int c4  = (t & 31) << 2;
            *(float4*)&Bs[row][c4] =
                *(const float4*)(B + (size_t)(k0 + row) * N + bn + c4);
        }
        __syncthreads();

        #pragma unroll
        for (int kk = 0; kk < 16; kk++) {
            float ra[8], rb[8];
            *(float4*)&ra[0] = *(const float4*)&As[kk][ty * 8];
            *(float4*)&ra[4] = *(const float4*)&As[kk][ty * 8 + 4];
            *(float4*)&rb[0] = *(const float4*)&Bs[kk][tx * 8];
            *(float4*)&rb[4] = *(const float4*)&Bs[kk][tx * 8 + 4];
            #pragma unroll
            for (int i = 0; i < 8; i++)
                #pragma unroll
                for (int j = 0; j < 8; j++)
                    acc[i][j] = fmaf(ra[i], rb[j], acc[i][j]);
        }
        __syncthreads();
    }

    #pragma unroll
    for (int i = 0; i < 8; i++) {
        int gr = bm + ty * 8 + i;
        if (gr >= M) continue;
        int n = gr / LTOK;
        int l = gr - n * LTOK;
        #pragma unroll
        for (int j = 0; j < 8; j++) {
            int col = bn + tx * 8 + j;
            int s   = col / DIMM;
            int rem = col - s * DIMM;
            int h   = rem >> 5;
            int c   = rem & 31;
            float* dst = (s == 0) ? g_q : ((s == 1) ? g_k : g_v);
            dst[(((size_t)(n * NHEAD + h)) * LTOK + l) * HEADD + c] = acc[i][j];
        }
    }
}

// ======================================================================
// Output projection: g_ao [21952 x 384] @ [384 x 384] + bias -> d_out
// ======================================================================
__global__ __launch_bounds__(256)
void proj_gemm_kernel(const float* __restrict__ B,
                      const float* __restrict__ bias,
                      float* __restrict__ C)
{
    __shared__ float As[16][132];
    __shared__ float Bs[16][132];

    const int M = MROWS, N = DIMM, K = DIMM;
    const int bm  = blockIdx.x * 128;
    const int bn  = blockIdx.y * 128;
    const int tid = threadIdx.x;
    const int tx  = tid & 15;
    const int ty  = tid >> 4;

    float acc[8][8];
    #pragma unroll
    for (int i = 0; i < 8; i++)
        #pragma unroll
        for (int j = 0; j < 8; j++) acc[i][j] = 0.f;

    for (int k0 = 0; k0 < K; k0 += 16) {
        #pragma unroll
        for (int i = 0; i < 2; i++) {
            int t   = tid + i * 256;
            int row = t >> 2;
            int c4  = (t & 3) << 2;
            int gr  = bm + row;
            float4 av = make_float4(0.f, 0.f, 0.f, 0.f);
            if (gr < M) av = *(const float4*)(g_ao + (size_t)gr * K + k0 + c4);
            As[c4 + 0][row] = av.x;
            As[c4 + 1][row] = av.y;
            As[c4 + 2][row] = av.z;
            As[c4 + 3][row] = av.w;
        }
        #pragma unroll
        for (int i = 0; i < 2; i++) {
            int t   = tid + i * 256;
            int row = t >> 5;
            int c4  = (t & 31) << 2;
            *(float4*)&Bs[row][c4] =
                *(const float4*)(B + (size_t)(k0 + row) * N + bn + c4);
        }
        __syncthreads();

        #pragma unroll
        for (int kk = 0; kk < 16; kk++) {
            float ra[8], rb[8];
            *(float4*)&ra[0] = *(const float4*)&As[kk][ty * 8];
            *(float4*)&ra[4] = *(const float4*)&As[kk][ty * 8 + 4];
            *(float4*)&rb[0] = *(const float4*)&Bs[kk][tx * 8];
            *(float4*)&rb[4] = *(const float4*)&Bs[kk][tx * 8 + 4];
            #pragma unroll
            for (int i = 0; i < 8; i++)
                #pragma unroll
                for (int j = 0; j < 8; j++)
                    acc[i][j] = fmaf(ra[i], rb[j], acc[i][j]);
        }
        __syncthreads();
    }

    #pragma unroll
    for (int i = 0; i < 8; i++) {
        int gr = bm + ty * 8 + i;
        if (gr >= M) continue;
        int col0 = bn + tx * 8;
        float4 b0 = *(const float4*)&bias[col0];
        float4 b1 = *(const float4*)&bias[col0 + 4];
        float4 o0 = make_float4(acc[i][0] + b0.x, acc[i][1] + b0.y,
                                acc[i][2] + b0.z, acc[i][3] + b0.w);
        float4 o1 = make_float4(acc[i][4] + b1.x, acc[i][5] + b1.y,
                                acc[i][6] + b1.z, acc[i][7] + b1.w);
        float* crow = C + (size_t)gr * N + col0;
        *(float4*)crow       = o0;
        *(float4*)(crow + 4) = o1;
    }
}

// ======================================================================
// Fused window attention: one block (512 thr) per (window, head).
// Score stage: 2 q-rows in registers per warp-task, lanes stride k.
// AV: 1q x 4ch per thread, one pass, vectorized S.
// ======================================================================
__global__ __launch_bounds__(512)
void attn_kernel(const void* __restrict__ mask)
{
    extern __shared__ float sm[];
    float* Ks = sm;                       // [343][36]
    float* Vs = Ks + LTOK * 36;           // [344][36]  (row 343 zeroed)
    float* Qs = Vs + 344 * 36;            // [64][36]
    float* Ss = Qs + 64 * 36;             // [64][344]  (col 343 zeroed)

    const int tid  = threadIdx.x;
    const int warp = tid >> 5;
    const int lane = tid & 31;
    const int bh   = blockIdx.x;
    const int n    = bh / NHEAD;
    const int h    = bh - n * NHEAD;

    const int mmode = g_mask_mode;
    const unsigned char* mb8 =
        (const unsigned char*)mask + (size_t)n * LTOK * LTOK;
    const unsigned int* mb32 =
        (const unsigned int*)mask + (size_t)n * LTOK * LTOK;
    const float* bias_h = g_bias + (size_t)h * LTOK * LTOK;

    // load K, V
    const float* kg = g_k + (size_t)bh * LTOK * HEADD;
    const float* vg = g_v + (size_t)bh * LTOK * HEADD;
    for (int i = tid; i < LTOK * 8; i += 512) {
        int row = i >> 3, c4 = (i & 7) << 2;
        *(float4*)&Ks[row * 36 + c4] = *(const float4*)(kg + (size_t)i * 4);
        *(float4*)&Vs[row * 36 + c4] = *(const float4*)(vg + (size_t)i * 4);
    }
    if (tid < 36) Vs[343 * 36 + tid] = 0.f;     // zero pad row
    __syncthreads();

    const float* qg = g_q + (size_t)bh * LTOK * HEADD;

    for (int q0 = 0; q0 < LTOK; q0 += 64) {
        const int qn = min(64, LTOK - q0);

        // Q tile
        for (int i = tid; i < qn * 8; i += 512) {
            int row = i >> 3, c4 = (i & 7) << 2;
            *(float4*)&Qs[row * 36 + c4] =
                *(const float4*)(qg + (size_t)q0 * HEADD + (size_t)i * 4);
        }
        __syncthreads();

        // ---- scores: warp handles q-pairs, Q held in registers ----
        for (int g2 = warp; g2 * 2 < qn; g2 += 16) {
            const int qi0 = g2 * 2;
            const bool has1 = (qi0 + 1) < qn;
            float4 Q0[8], Q1[8];
            const float* r0 = Qs + qi0 * 36;
            const float* r1 = Qs + (has1 ? (qi0 + 1) : qi0) * 36;
            #pragma unroll
            for (int c = 0; c < 8; c++) {
                Q0[c] = *(const float4*)(r0 + c * 4);
                Q1[c] = *(const float4*)(r1 + c * 4);
            }
            const size_t grow0 = (size_t)(q0 + qi0) * LTOK;
            float* s0 = Ss + qi0 * 344;
            float* s1 = s0 + 344;

            for (int kj = lane; kj < LTOK; kj += 32) {
                const float* krow = Ks + kj * 36;
                float a0 = 0.f, a1 = 0.f;
                #pragma unroll
                for (int c = 0; c < 8; c++) {
                    float4 kv = *(const float4*)(krow + c * 4);
                    a0 += Q0[c].x * kv.x + Q0[c].y * kv.y
                        + Q0[c].z * kv.z + Q0[c].w * kv.w;
                    a1 += Q1[c].x * kv.x + Q1[c].y * kv.y
                        + Q1[c].z * kv.z + Q1[c].w * kv.w;
                }
                size_t off0 = grow0 + kj;
                bool m0 = mmode ? (mb32[off0] != 0u) : (mb8[off0] != 0);
                s0[kj] = m0 ? -1e30f : fmaf(a0, QSCALE, bias_h[off0]);
                if (has1) {
                    size_t off1 = off0 + LTOK;
                    bool m1 = mmode ? (mb32[off1] != 0u) : (mb8[off1] != 0);
                    s1[kj] = m1 ? -1e30f : fmaf(a1, QSCALE, bias_h[off1]);
                }
            }
        }
        __syncthreads();

        // ---- softmax: one warp per row ----
        for (int row = warp; row < qn; row += 16) {
            float* sr = Ss + row * 344;
            float m = -1e30f;
            for (int j = lane; j < LTOK; j += 32) m = fmaxf(m, sr[j]);
            #pragma unroll
            for (int off = 16; off > 0; off >>= 1)
                m = fmaxf(m, __shfl_xor_sync(0xffffffffu, m, off));
            float ssum = 0.f;
            for (int j = lane; j < LTOK; j += 32) {
                float e = __expf(sr[j] - m);
                sr[j] = e;
                ssum += e;
            }
            #pragma unroll
            for (int off = 16; off > 0; off >>= 1)
                ssum += __shfl_xor_sync(0xffffffffu, ssum, off);
            float inv = 1.f / ssum;
            for (int j = lane; j < LTOK; j += 32) sr[j] *= inv;
            if (lane == 0) sr[343] = 0.f;   // pad for vectorized AV
        }
        __syncthreads();

        // ---- AV: thread = (q, 4-channel group), single pass ----
        {
            int q  = tid >> 3;
            int cg = tid & 7;
            if (q < qn) {
                const float* sr   = Ss + q * 344;
                const float* vcol = Vs + cg * 4;
                float4 acc = make_float4(0.f, 0.f, 0.f, 0.f);
                #pragma unroll 2
                for (int j0 = 0; j0 < 344; j0 += 4) {
                    float4 sv = *(const float4*)(sr + j0);
                    float4 v0 = *(const float4*)(vcol + (size_t)(j0 + 0) * 36);
                    float4 v1 = *(const float4*)(vcol + (size_t)(j0 + 1) * 36);
                    float4 v2 = *(const float4*)(vcol + (size_t)(j0 + 2) * 36);
                    float4 v3 = *(const float4*)(vcol + (size_t)(j0 + 3) * 36);
                    acc.x = fmaf(sv.x, v0.x, acc.x);
                    acc.y = fmaf(sv.x, v0.y, acc.y);
                    acc.z = fmaf(sv.x, v0.z, acc.z);
                    acc.w = fmaf(sv.x, v0.w, acc.w);
                    acc.x = fmaf(sv.y, v1.x, acc.x);
                    acc.y = fmaf(sv.y, v1.y, acc.y);
                    acc.z = fmaf(sv.y, v1.z, acc.z);
                    acc.w = fmaf(sv.y, v1.w, acc.w);
                    acc.x = fmaf(sv.z, v2.x, acc.x);
                    acc.y = fmaf(sv.z, v2.y, acc.y);
                    acc.z = fmaf(sv.z, v2.z, acc.z);
                    acc.w = fmaf(sv.z, v2.w, acc.w);
                    acc.x = fmaf(sv.w, v3.x, acc.x);
                    acc.y = fmaf(sv.w, v3.y, acc.y);
                    acc.z = fmaf(sv.w, v3.z, acc.z);
                    acc.w = fmaf(sv.w, v3.w, acc.w);
                }
                float* og = g_ao + ((size_t)(n * LTOK + q0 + q)) * DIMM
                            + h * HEADD + cg * 4;
                *(float4*)og = acc;
            }
        }
        __syncthreads();
    }
}

// ======================================================================
extern "C" void kernel_launch(void* const* d_in, const int* in_sizes, int n_in,
                              void* d_out, int out_size)
{
    const float *x = nullptr, *qkvw = nullptr, *tbl = nullptr;
    const float *pw = nullptr, *pb = nullptr;
    const void* mask = nullptr;
    const int* ridx = nullptr;
    for (int i = 0; i < n_in; i++) {
        switch (in_sizes[i]) {
            case 8429568:  x    = (const float*)d_in[i]; break;
            case 442368:   qkvw = (const float*)d_in[i]; break;
            case 26364:    tbl  = (const float*)d_in[i]; break;
            case 147456:   pw   = (const float*)d_in[i]; break;
            case 384:      pb   = (const float*)d_in[i]; break;
            case 7530496:  mask = d_in[i]; break;
            case 117649:   ridx = (const int*)d_in[i]; break;
        }
    }
    if (n_in >= 7) {
        if (!x)    x    = (const float*)d_in[0];
        if (!qkvw) qkvw = (const float*)d_in[1];
        if (!tbl)  tbl  = (const float*)d_in[2];
        if (!pw)   pw   = (const float*)d_in[3];
        if (!pb)   pb   = (const float*)d_in[4];
        if (!mask) mask = d_in[5];
        if (!ridx) ridx = (const int*)d_in[6];
    }

    // 0) mask dtype detection + bias precompute
    detect_mask_kernel<<<1, 256>>>((const unsigned int*)mask);
    bias_prep_kernel<<<(LTOK * LTOK + 255) / 256, 256>>>(tbl, ridx);

    // 1) QKV projection + scatter to [n][h][l][c]
    qkv_gemm_kernel<<<dim3(172, 9), 256>>>(x, qkvw);

    // 2) fused attention
    size_t smem = (size_t)(LTOK * 36 + 344 * 36 + 64 * 36 + 64 * 344)
                  * sizeof(float);
    cudaFuncSetAttribute(attn_kernel,
                         cudaFuncAttributeMaxDynamicSharedMemorySize, (int)smem);
    attn_kernel<<<NWIN * NHEAD, 512, smem>>>(mask);

    // 3) output projection + bias
    proj_gemm_kernel<<<dim3(172, 3), 256>>>(pw, pb, (float*)d_out);
}

// round 6
// speedup vs baseline: 1.6446x; 1.1229x over previous
#include <cuda_runtime.h>

#define NWIN  64
#define NHEAD 12
#define LTOK  343
#define HEADD 32
#define DIMM  384
#define TBLN  2197
#define L2TOK (LTOK*LTOK)
#define QSCALE 0.17677669529663687f   // 32^-0.5
#define MROWS (NWIN*LTOK)             // 21952

// -------- scratch (static device globals; no runtime allocation) --------
__device__ __align__(16) float g_q[(size_t)NWIN*NHEAD*LTOK*HEADD];
__device__ __align__(16) float g_k[(size_t)NWIN*NHEAD*LTOK*HEADD];
__device__ __align__(16) float g_v[(size_t)NWIN*NHEAD*LTOK*HEADD];
__device__ __align__(16) float g_ao[(size_t)MROWS*DIMM];
__device__ __align__(16) float g_biasT[(size_t)NHEAD*L2TOK];        // [h][j][i]
__device__ __align__(16) unsigned char g_maskT[(size_t)NWIN*L2TOK]; // [n][j][i]
__device__ int g_mask_mode;   // 0 = 1-byte elements, 1 = 4-byte elements

// ======================================================================
__global__ void detect_mask_kernel(const unsigned int* __restrict__ m)
{
    __shared__ int s_not01, s_notf;
    if (threadIdx.x == 0) { s_not01 = 0; s_notf = 0; }
    __syncthreads();
    int bad01 = 0, badf = 0;
    for (int i = threadIdx.x; i < 4096; i += 256) {
        unsigned int w = m[i];
        if (w > 1u) bad01 = 1;
        if (w != 0u && w != 0x3F800000u) badf = 1;
    }
    if (bad01) atomicOr(&s_not01, 1);
    if (badf)  atomicOr(&s_notf, 1);
    __syncthreads();
    if (threadIdx.x == 0)
        g_mask_mode = (!s_not01 || !s_notf) ? 1 : 0;
}

// ======================================================================
// biasT[h][j][i] = table[rel_idx[i][j]][h]   (coalesced writes)
// ======================================================================
__global__ __launch_bounds__(256)
void biast_prep_kernel(const float* __restrict__ table,
                       const int* __restrict__ rel_idx)
{
    int e = blockIdx.x * 256 + threadIdx.x;     // e = j*LTOK + i
    if (e < L2TOK) {
        int j = e / LTOK, i = e - j * LTOK;
        int idx = rel_idx[(size_t)i * LTOK + j];
        #pragma unroll
        for (int h = 0; h < NHEAD; h++)
            g_biasT[(size_t)h * L2TOK + e] = table[(size_t)idx * NHEAD + h];
    }
}

// ======================================================================
// maskT[n][j][i] = mask[n][i][j] != 0   (uint8, coalesced writes)
// ======================================================================
__global__ __launch_bounds__(256)
void maskt_prep_kernel(const void* __restrict__ mask)
{
    int n = blockIdx.y;
    int e = blockIdx.x * 256 + threadIdx.x;
    if (e < L2TOK) {
        int j = e / LTOK, i = e - j * LTOK;
        size_t src = (size_t)n * L2TOK + (size_t)i * LTOK + j;
        bool mm = g_mask_mode
                      ? (((const unsigned int*)mask)[src] != 0u)
                      : (((const unsigned char*)mask)[src] != 0);
        g_maskT[(size_t)n * L2TOK + e] = mm ? 1 : 0;
    }
}

// ======================================================================
// QKV GEMM (unchanged)
// ======================================================================
__global__ __launch_bounds__(256)
void qkv_gemm_kernel(const float* __restrict__ A, const float* __restrict__ B)
{
    __shared__ float As[16][132];
    __shared__ float Bs[16][132];

    const int M = MROWS, N = 3 * DIMM, K = DIMM;
    const int bm  = blockIdx.x * 128;
    const int bn  = blockIdx.y * 128;
    const int tid = threadIdx.x;
    const int tx  = tid & 15;
    const int ty  = tid >> 4;

    float acc[8][8];
    #pragma unroll
    for (int i = 0; i < 8; i++)
        #pragma unroll
        for (int j = 0; j < 8; j++) acc[i][j] = 0.f;

    for (int k0 = 0; k0 < K; k0 += 16) {
        #pragma unroll
        for (int i = 0; i < 2; i++) {
            int t   = tid + i * 256;
            int row = t >> 2;
            int c4  = (t & 3) << 2;
            int gr  = bm + row;
            float4 av = make_float4(0.f, 0.f, 0.f, 0.f);
            if (gr < M) av = *(const float4*)(A + (size_t)gr * K + k0 + c4);
            As[c4 + 0][row] = av.x;
            As[c4 + 1][row] = av.y;
            As[c4 + 2][row] = av.z;
            As[c4 + 3][row] = av.w;
        }
        #pragma unroll
        for (int i = 0; i < 2; i++) {
            int t   = tid + i * 256;
            int row = t >> 5;
            int c4  = (t & 31) << 2;
            *(float4*)&Bs[row][c4] =
                *(const float4*)(B + (size_t)(k0 + row) * N + bn + c4);
        }
        __syncthreads();

        #pragma unroll
        for (int kk = 0; kk < 16; kk++) {
            float ra[8], rb[8];
            *(float4*)&ra[0] = *(const float4*)&As[kk][ty * 8];
            *(float4*)&ra[4] = *(const float4*)&As[kk][ty * 8 + 4];
            *(float4*)&rb[0] = *(const float4*)&Bs[kk][tx * 8];
            *(float4*)&rb[4] = *(const float4*)&Bs[kk][tx * 8 + 4];
            #pragma unroll
            for (int i = 0; i < 8; i++)
                #pragma unroll
                for (int j = 0; j < 8; j++)
                    acc[i][j] = fmaf(ra[i], rb[j], acc[i][j]);
        }
        __syncthreads();
    }

    #pragma unroll
    for (int i = 0; i < 8; i++) {
        int gr = bm + ty * 8 + i;
        if (gr >= M) continue;
        int n = gr / LTOK;
        int l = gr - n * LTOK;
        #pragma unroll
        for (int j = 0; j < 8; j++) {
            int col = bn + tx * 8 + j;
            int s   = col / DIMM;
            int rem = col - s * DIMM;
            int h   = rem >> 5;
            int c   = rem & 31;
            float* dst = (s == 0) ? g_q : ((s == 1) ? g_k : g_v);
            dst[(((size_t)(n * NHEAD + h)) * LTOK + l) * HEADD + c] = acc[i][j];
        }
    }
}

// ======================================================================
// Output projection (unchanged)
// ======================================================================
__global__ __launch_bounds__(256)
void proj_gemm_kernel(const float* __restrict__ B,
                      const float* __restrict__ bias,
                      float* __restrict__ C)
{
    __shared__ float As[16][132];
    __shared__ float Bs[16][132];

    const int M = MROWS, N = DIMM, K = DIMM;
    const int bm  = blockIdx.x * 128;
    const int bn  = blockIdx.y * 128;
    const int tid = threadIdx.x;
    const int tx  = tid & 15;
    const int ty  = tid >> 4;

    float acc[8][8];
    #pragma unroll
    for (int i = 0; i < 8; i++)
        #pragma unroll
        for (int j = 0; j < 8; j++) acc[i][j] = 0.f;

    for (int k0 = 0; k0 < K; k0 += 16) {
        #pragma unroll
        for (int i = 0; i < 2; i++) {
            int t   = tid + i * 256;
            int row = t >> 2;
            int c4  = (t & 3) << 2;
            int gr  = bm + row;
            float4 av = make_float4(0.f, 0.f, 0.f, 0.f);
            if (gr < M) av = *(const float4*)(g_ao + (size_t)gr * K + k0 + c4);
            As[c4 + 0][row] = av.x;
            As[c4 + 1][row] = av.y;
            As[c4 + 2][row] = av.z;
            As[c4 + 3][row] = av.w;
        }
        #pragma unroll
        for (int i = 0; i < 2; i++) {
            int t   = tid + i * 256;
            int row = t >> 5;
            int c4  = (t & 31) << 2;
            *(float4*)&Bs[row][c4] =
                *(const float4*)(B + (size_t)(k0 + row) * N + bn + c4);
        }
        __syncthreads();

        #pragma unroll
        for (int kk = 0; kk < 16; kk++) {
            float ra[8], rb[8];
            *(float4*)&ra[0] = *(const float4*)&As[kk][ty * 8];
            *(float4*)&ra[4] = *(const float4*)&As[kk][ty * 8 + 4];
            *(float4*)&rb[0] = *(const float4*)&Bs[kk][tx * 8];
            *(float4*)&rb[4] = *(const float4*)&Bs[kk][tx * 8 + 4];
            #pragma unroll
            for (int i = 0; i < 8; i++)
                #pragma unroll
                for (int j = 0; j < 8; j++)
                    acc[i][j] = fmaf(ra[i], rb[j], acc[i][j]);
        }
        __syncthreads();
    }

    #pragma unroll
    for (int i = 0; i < 8; i++) {
        int gr = bm + ty * 8 + i;
        if (gr >= M) continue;
        int col0 = bn + tx * 8;
        float4 b0 = *(const float4*)&bias[col0];
        float4 b1 = *(const float4*)&bias[col0 + 4];
        float4 o0 = make_float4(acc[i][0] + b0.x, acc[i][1] + b0.y,
                                acc[i][2] + b0.z, acc[i][3] + b0.w);
        float4 o1 = make_float4(acc[i][4] + b1.x, acc[i][5] + b1.y,
                                acc[i][6] + b1.z, acc[i][7] + b1.w);
        float* crow = C + (size_t)gr * N + col0;
        *(float4*)crow       = o0;
        *(float4*)(crow + 4) = o1;
    }
}

// ======================================================================
// Fused window attention v2: block(512) per (window, head).
// Score: lane-owns-q, K broadcast, online max. Probs stored transposed.
// AV: 4q x 4c register tiles.
// ======================================================================
__global__ __launch_bounds__(512)
void attn_kernel()
{
    extern __shared__ float sm[];
    float* Ks  = sm;                      // [343][36]
    float* Vs  = Ks + LTOK * 36;          // [343][36]
    float* SsT = Vs + LTOK * 36;          // [343][64]  transposed scores/probs
    float* Red = SsT + LTOK * 64;         // [8][64] partial max/sum
    float* Mf  = Red + 8 * 64;            // [64] final max
    float* Sf  = Mf + 64;                 // [64] 1/sum

    const int tid  = threadIdx.x;
    const int warp = tid >> 5;
    const int lane = tid & 31;
    const int bh   = blockIdx.x;
    const int n    = bh / NHEAD;
    const int h    = bh - n * NHEAD;

    const int g  = warp >> 3;             // q half (0/1)
    const int r  = warp & 7;              // kj range id
    const int k0r = r * 43;
    const int k1r = min(k0r + 43, LTOK);
    const int qt  = g * 32 + lane;        // q index within tile

    const float* bias_h = g_biasT + (size_t)h * L2TOK;
    const unsigned char* mT = g_maskT + (size_t)n * L2TOK;

    // load K, V tiles
    const float* kg = g_k + (size_t)bh * LTOK * HEADD;
    const float* vg = g_v + (size_t)bh * LTOK * HEADD;
    for (int i = tid; i < LTOK * 8; i += 512) {
        int row = i >> 3, c4 = (i & 7) << 2;
        *(float4*)&Ks[row * 36 + c4] = *(const float4*)(kg + (size_t)i * 4);
        *(float4*)&Vs[row * 36 + c4] = *(const float4*)(vg + (size_t)i * 4);
    }
    __syncthreads();

    const float* qg = g_q + (size_t)bh * LTOK * HEADD;

    for (int q0 = 0; q0 < LTOK; q0 += 64) {
        const int qn = min(64, LTOK - q0);
        const int qglob = q0 + qt;

        // lane's query row into registers (clamped for invalid lanes)
        float4 Q[8];
        {
            const float* qrow = qg + (size_t)min(qglob, LTOK - 1) * HEADD;
            #pragma unroll
            for (int c = 0; c < 8; c++) Q[c] = *(const float4*)(qrow + c * 4);
        }

        // ---- scores + online max ----
        float mloc = -1e30f;
        for (int kj = k0r; kj < k1r; kj++) {
            const float* krow = Ks + kj * 36;
            float p0 = 0.f, p1 = 0.f, p2 = 0.f, p3 = 0.f;
            #pragma unroll
            for (int c = 0; c < 2; c++) {
                float4 k0 = *(const float4*)(krow + (c * 4 + 0) * 4);
                float4 k1 = *(const float4*)(krow + (c * 4 + 1) * 4);
                float4 k2 = *(const float4*)(krow + (c * 4 + 2) * 4);
                float4 k3 = *(const float4*)(krow + (c * 4 + 3) * 4);
                float4 q0v = Q[c * 4 + 0], q1v = Q[c * 4 + 1];
                float4 q2v = Q[c * 4 + 2], q3v = Q[c * 4 + 3];
                p0 = fmaf(q0v.x, k0.x, fmaf(q0v.y, k0.y,
                     fmaf(q0v.z, k0.z, fmaf(q0v.w, k0.w, p0))));
                p1 = fmaf(q1v.x, k1.x, fmaf(q1v.y, k1.y,
                     fmaf(q1v.z, k1.z, fmaf(q1v.w, k1.w, p1))));
                p2 = fmaf(q2v.x, k2.x, fmaf(q2v.y, k2.y,
                     fmaf(q2v.z, k2.z, fmaf(q2v.w, k2.w, p2))));
                p3 = fmaf(q3v.x, k3.x, fmaf(q3v.y, k3.y,
                     fmaf(q3v.z, k3.z, fmaf(q3v.w, k3.w, p3))));
            }
            float dot = (p0 + p1) + (p2 + p3);
            size_t off = (size_t)kj * LTOK + qglob;
            float s = mT[off] ? -1e30f : fmaf(dot, QSCALE, bias_h[off]);
            mloc = fmaxf(mloc, s);
            SsT[kj * 64 + qt] = s;
        }
        Red[r * 64 + qt] = mloc;
        __syncthreads();

        if (tid < 64) {
            float m = Red[tid];
            #pragma unroll
            for (int rr = 1; rr < 8; rr++) m = fmaxf(m, Red[rr * 64 + tid]);
            Mf[tid] = m;
        }
        __syncthreads();

        // ---- exp + partial sum (probs written back) ----
        {
            float mq = Mf[qt];
            float ssum = 0.f;
            for (int kj = k0r; kj < k1r; kj++) {
                float p = __expf(SsT[kj * 64 + qt] - mq);
                SsT[kj * 64 + qt] = p;
                ssum += p;
            }
            Red[r * 64 + qt] = ssum;
        }
        __syncthreads();

        if (tid < 64) {
            float s = Red[tid];
            #pragma unroll
            for (int rr = 1; rr < 8; rr++) s += Red[rr * 64 + tid];
            Sf[tid] = 1.f / s;
        }
        __syncthreads();

        // ---- AV: 128 threads, 4q x 4c register tiles ----
        if (tid < 128) {
            int qgp = tid >> 3;           // 0..15 : q-group of 4
            int cg  = tid & 7;            // 0..7  : channel group of 4
            float4 a0 = make_float4(0.f, 0.f, 0.f, 0.f);
            float4 a1 = make_float4(0.f, 0.f, 0.f, 0.f);
            float4 a2 = make_float4(0.f, 0.f, 0.f, 0.f);
            float4 a3 = make_float4(0.f, 0.f, 0.f, 0.f);
            const float* sp = SsT + qgp * 4;
            const float* vp = Vs + cg * 4;
            #pragma unroll 4
            for (int j = 0; j < LTOK; j++) {
                float4 pv = *(const float4*)(sp + j * 64);
                float4 vv = *(const float4*)(vp + j * 36);
                a0.x = fmaf(pv.x, vv.x, a0.x);
                a0.y = fmaf(pv.x, vv.y, a0.y);
                a0.z = fmaf(pv.x, vv.z, a0.z);
                a0.w = fmaf(pv.x, vv.w, a0.w);
                a1.x = fmaf(pv.y, vv.x, a1.x);
                a1.y = fmaf(pv.y, vv.y, a1.y);
                a1.z = fmaf(pv.y, vv.z, a1.z);
                a1.w = fmaf(pv.y, vv.w, a1.w);
                a2.x = fmaf(pv.z, vv.x, a2.x);
                a2.y = fmaf(pv.z, vv.y, a2.y);
                a2.z = fmaf(pv.z, vv.z, a2.z);
                a2.w = fmaf(pv.z, vv.w, a2.w);
                a3.x = fmaf(pv.w, vv.x, a3.x);
                a3.y = fmaf(pv.w, vv.y, a3.y);
                a3.z = fmaf(pv.w, vv.z, a3.z);
                a3.w = fmaf(pv.w, vv.w, a3.w);
            }
            float4 accs[4] = {a0, a1, a2, a3};
            #pragma unroll
            for (int i = 0; i < 4; i++) {
                int qi = qgp * 4 + i;
                if (qi < qn) {
                    float inv = Sf[qi];
                    float4 o = make_float4(accs[i].x * inv, accs[i].y * inv,
                                           accs[i].z * inv, accs[i].w * inv);
                    float* og = g_ao + ((size_t)(n * LTOK + q0 + qi)) * DIMM
                                + h * HEADD + cg * 4;
                    *(float4*)og = o;
                }
            }
        }
        __syncthreads();
    }
}

// ======================================================================
extern "C" void kernel_launch(void* const* d_in, const int* in_sizes, int n_in,
                              void* d_out, int out_size)
{
    const float *x = nullptr, *qkvw = nullptr, *tbl = nullptr;
    const float *pw = nullptr, *pb = nullptr;
    const void* mask = nullptr;
    const int* ridx = nullptr;
    for (int i = 0; i < n_in; i++) {
        switch (in_sizes[i]) {
            case 8429568:  x    = (const float*)d_in[i]; break;
            case 442368:   qkvw = (const float*)d_in[i]; break;
            case 26364:    tbl  = (const float*)d_in[i]; break;
            case 147456:   pw   = (const float*)d_in[i]; break;
            case 384:      pb   = (const float*)d_in[i]; break;
            case 7530496:  mask = d_in[i]; break;
            case 117649:   ridx = (const int*)d_in[i]; break;
        }
    }
    if (n_in >= 7) {
        if (!x)    x    = (const float*)d_in[0];
        if (!qkvw) qkvw = (const float*)d_in[1];
        if (!tbl)  tbl  = (const float*)d_in[2];
        if (!pw)   pw   = (const float*)d_in[3];
        if (!pb)   pb   = (const float*)d_in[4];
        if (!mask) mask = d_in[5];
        if (!ridx) ridx = (const int*)d_in[6];
    }

    // 0) prep: mask dtype, transposed bias / mask
    detect_mask_kernel<<<1, 256>>>((const unsigned int*)mask);
    int nb = (L2TOK + 255) / 256;
    biast_prep_kernel<<<nb, 256>>>(tbl, ridx);
    maskt_prep_kernel<<<dim3(nb, NWIN), 256>>>(mask);

    // 1) QKV projection + scatter to [n][h][l][c]
    qkv_gemm_kernel<<<dim3(172, 9), 256>>>(x, qkvw);

    // 2) fused attention
    size_t smem = (size_t)(LTOK * 36 * 2 + LTOK * 64 + 8 * 64 + 128)
                  * sizeof(float);
    cudaFuncSetAttribute(attn_kernel,
                         cudaFuncAttributeMaxDynamicSharedMemorySize, (int)smem);
    attn_kernel<<<NWIN * NHEAD, 512, smem>>>();

    // 3) output projection + bias
    proj_gemm_kernel<<<dim3(172, 3), 256>>>(pw, pb, (float*)d_out);
}

// round 7
// speedup vs baseline: 2.0404x; 1.2407x over previous
#include <cuda_runtime.h>

#define NWIN  64
#define NHEAD 12
#define LTOK  343
#define HEADD 32
#define DIMM  384
#define TBLN  2197
#define L2TOK (LTOK*LTOK)
#define QSCALE 0.17677669529663687f   // 32^-0.5
#define MROWS (NWIN*LTOK)             // 21952

// -------- scratch (static device globals; no runtime allocation) --------
__device__ __align__(16) float g_q[(size_t)NWIN*NHEAD*LTOK*HEADD];
__device__ __align__(16) float g_k[(size_t)NWIN*NHEAD*LTOK*HEADD];
__device__ __align__(16) float g_v[(size_t)NWIN*NHEAD*LTOK*HEADD];
__device__ __align__(16) float g_ao[(size_t)MROWS*DIMM];
__device__ __align__(16) float g_biasT[(size_t)NHEAD*L2TOK];        // [h][j][i]
__device__ __align__(16) unsigned char g_maskT[(size_t)NWIN*L2TOK]; // [n][j][i]
__device__ int g_mask_mode;   // 0 = 1-byte elements, 1 = 4-byte elements

// ======================================================================
__global__ void detect_mask_kernel(const unsigned int* __restrict__ m)
{
    __shared__ int s_not01, s_notf;
    if (threadIdx.x == 0) { s_not01 = 0; s_notf = 0; }
    __syncthreads();
    int bad01 = 0, badf = 0;
    for (int i = threadIdx.x; i < 4096; i += 256) {
        unsigned int w = m[i];
        if (w > 1u) bad01 = 1;
        if (w != 0u && w != 0x3F800000u) badf = 1;
    }
    if (bad01) atomicOr(&s_not01, 1);
    if (badf)  atomicOr(&s_notf, 1);
    __syncthreads();
    if (threadIdx.x == 0)
        g_mask_mode = (!s_not01 || !s_notf) ? 1 : 0;
}

// ======================================================================
__global__ __launch_bounds__(256)
void biast_prep_kernel(const float* __restrict__ table,
                       const int* __restrict__ rel_idx)
{
    int e = blockIdx.x * 256 + threadIdx.x;     // e = j*LTOK + i
    if (e < L2TOK) {
        int j = e / LTOK, i = e - j * LTOK;
        int idx = rel_idx[(size_t)i * LTOK + j];
        #pragma unroll
        for (int h = 0; h < NHEAD; h++)
            g_biasT[(size_t)h * L2TOK + e] = table[(size_t)idx * NHEAD + h];
    }
}

// ======================================================================
__global__ __launch_bounds__(256)
void maskt_prep_kernel(const void* __restrict__ mask)
{
    int n = blockIdx.y;
    int e = blockIdx.x * 256 + threadIdx.x;
    if (e < L2TOK) {
        int j = e / LTOK, i = e - j * LTOK;
        size_t src = (size_t)n * L2TOK + (size_t)i * LTOK + j;
        bool mm = g_mask_mode
                      ? (((const unsigned int*)mask)[src] != 0u)
                      : (((const unsigned char*)mask)[src] != 0);
        g_maskT[(size_t)n * L2TOK + e] = mm ? 1 : 0;
    }
}

// ======================================================================
// tf32 helpers
// ======================================================================
__device__ __forceinline__ unsigned f2tf32(float f)
{
    unsigned r;
    asm("cvt.rna.tf32.f32 %0, %1;" : "=r"(r) : "f"(f));
    return r;
}

__device__ __forceinline__ void mma_tf32(float c[4], const unsigned a[4],
                                         const unsigned b[2])
{
    asm volatile(
        "mma.sync.aligned.m16n8k8.row.col.f32.tf32.tf32.f32 "
        "{%0,%1,%2,%3}, {%4,%5,%6,%7}, {%8,%9}, {%0,%1,%2,%3};"
        : "+f"(c[0]), "+f"(c[1]), "+f"(c[2]), "+f"(c[3])
        : "r"(a[0]), "r"(a[1]), "r"(a[2]), "r"(a[3]),
          "r"(b[0]), "r"(b[1]));
}

// ======================================================================
// tf32 tensor-core GEMM: C(M,N) = A(M,K) @ B(K,N)
// BM=128, BN=64, BK=16; 256 threads = 8 warps (4 x 2), 32x32 warp tile.
// mode 0: C[r*N+col] = acc + bias[col]     (A = g_ao)
// mode 1: scatter into g_q/g_k/g_v [n][h][l][c]   (A = Ain)
// Requires N % 64 == 0, K % 16 == 0. M edge guarded.
// ======================================================================
__global__ __launch_bounds__(256)
void mm_tf32_kernel(const float* __restrict__ Ain, const float* __restrict__ B,
                    int M, int N, int K, int mode,
                    float* __restrict__ C, const float* __restrict__ bias)
{
    __shared__ unsigned As[128][18];   // [m][k], padded
    __shared__ unsigned Bs[16][72];    // [k][n], padded

    const float* A = (mode == 0) ? g_ao : Ain;
    const int tid  = threadIdx.x;
    const int warp = tid >> 5, lane = tid & 31;
    const int wm   = warp & 3;         // m sub-tile (0..3) * 32
    const int wn   = warp >> 2;        // n sub-tile (0..1) * 32
    const int gid  = lane >> 2, tig = lane & 3;
    const int bm   = blockIdx.x * 128, bn = blockIdx.y * 64;

    float c[2][4][4];
    #pragma unroll
    for (int mt = 0; mt < 2; mt++)
        #pragma unroll
        for (int nt = 0; nt < 4; nt++)
            #pragma unroll
            for (int e = 0; e < 4; e++) c[mt][nt][e] = 0.f;

    for (int k0 = 0; k0 < K; k0 += 16) {
        // stage A tile (128 x 16)
        #pragma unroll
        for (int i = 0; i < 2; i++) {
            int t  = tid + i * 256;
            int m  = t >> 2;
            int c4 = (t & 3) << 2;
            int gr = bm + m;
            float4 v = make_float4(0.f, 0.f, 0.f, 0.f);
            if (gr < M) v = *(const float4*)(A + (size_t)gr * K + k0 + c4);
            As[m][c4 + 0] = f2tf32(v.x);
            As[m][c4 + 1] = f2tf32(v.y);
            As[m][c4 + 2] = f2tf32(v.z);
            As[m][c4 + 3] = f2tf32(v.w);
        }
        // stage B tile (16 x 64)
        {
            int kr = tid >> 4;
            int c4 = (tid & 15) << 2;
            float4 v = *(const float4*)(B + (size_t)(k0 + kr) * N + bn + c4);
            Bs[kr][c4 + 0] = f2tf32(v.x);
            Bs[kr][c4 + 1] = f2tf32(v.y);
            Bs[kr][c4 + 2] = f2tf32(v.z);
            Bs[kr][c4 + 3] = f2tf32(v.w);
        }
        __syncthreads();

        #pragma unroll
        for (int ks = 0; ks < 16; ks += 8) {
            unsigned af[2][4], bf[4][2];
            #pragma unroll
            for (int mt = 0; mt < 2; mt++) {
                int mr = wm * 32 + mt * 16 + gid;
                af[mt][0] = As[mr][ks + tig];
                af[mt][1] = As[mr + 8][ks + tig];
                af[mt][2] = As[mr][ks + tig + 4];
                af[mt][3] = As[mr + 8][ks + tig + 4];
            }
            #pragma unroll
            for (int nt = 0; nt < 4; nt++) {
                int nc = wn * 32 + nt * 8 + gid;
                bf[nt][0] = Bs[ks + tig][nc];
                bf[nt][1] = Bs[ks + tig + 4][nc];
            }
            #pragma unroll
            for (int mt = 0; mt < 2; mt++)
                #pragma unroll
                for (int nt = 0; nt < 4; nt++)
                    mma_tf32(c[mt][nt], af[mt], bf[nt]);
        }
        __syncthreads();
    }

    // ---- epilogue ----
    #pragma unroll
    for (int mt = 0; mt < 2; mt++) {
        int r0 = bm + wm * 32 + mt * 16 + gid;
        int r1 = r0 + 8;
        if (mode == 0) {
            #pragma unroll
            for (int nt = 0; nt < 4; nt++) {
                int col = bn + wn * 32 + nt * 8 + tig * 2;
                float bx = bias[col], by = bias[col + 1];
                if (r0 < M) {
                    float2 o = make_float2(c[mt][nt][0] + bx, c[mt][nt][1] + by);
                    *(float2*)(C + (size_t)r0 * N + col) = o;
                }
                if (r1 < M) {
                    float2 o = make_float2(c[mt][nt][2] + bx, c[mt][nt][3] + by);
                    *(float2*)(C + (size_t)r1 * N + col) = o;
                }
            }
        } else {
            int n0 = r0 / LTOK, l0 = r0 - n0 * LTOK;
            int n1 = r1 / LTOK, l1 = r1 - n1 * LTOK;
            #pragma unroll
            for (int nt = 0; nt < 4; nt++) {
                int colb = bn + wn * 32 + nt * 8 + tig * 2;
                #pragma unroll
                for (int e = 0; e < 4; e++) {
                    int row = (e < 2) ? r0 : r1;
                    if (row >= M) continue;
                    int nn  = (e < 2) ? n0 : n1;
                    int ll  = (e < 2) ? l0 : l1;
                    int col = colb + (e & 1);
                    int s   = col / DIMM;
                    int rem = col - s * DIMM;
                    int hh  = rem >> 5;
                    int cc  = rem & 31;
                    float* dst = (s == 0) ? g_q : ((s == 1) ? g_k : g_v);
                    dst[(((size_t)(nn * NHEAD + hh)) * LTOK + ll) * HEADD + cc]
                        = c[mt][nt][e];
                }
            }
        }
    }
}

// ======================================================================
// Fused window attention (unchanged from round 6)
// ======================================================================
__global__ __launch_bounds__(512)
void attn_kernel()
{
    extern __shared__ float sm[];
    float* Ks  = sm;                      // [343][36]
    float* Vs  = Ks + LTOK * 36;          // [343][36]
    float* SsT = Vs + LTOK * 36;          // [343][64]
    float* Red = SsT + LTOK * 64;         // [8][64]
    float* Mf  = Red + 8 * 64;            // [64]
    float* Sf  = Mf + 64;                 // [64]

    const int tid  = threadIdx.x;
    const int warp = tid >> 5;
    const int lane = tid & 31;
    const int bh   = blockIdx.x;
    const int n    = bh / NHEAD;
    const int h    = bh - n * NHEAD;

    const int g  = warp >> 3;
    const int r  = warp & 7;
    const int k0r = r * 43;
    const int k1r = min(k0r + 43, LTOK);
    const int qt  = g * 32 + lane;

    const float* bias_h = g_biasT + (size_t)h * L2TOK;
    const unsigned char* mT = g_maskT + (size_t)n * L2TOK;

    const float* kg = g_k + (size_t)bh * LTOK * HEADD;
    const float* vg = g_v + (size_t)bh * LTOK * HEADD;
    for (int i = tid; i < LTOK * 8; i += 512) {
        int row = i >> 3, c4 = (i & 7) << 2;
        *(float4*)&Ks[row * 36 + c4] = *(const float4*)(kg + (size_t)i * 4);
        *(float4*)&Vs[row * 36 + c4] = *(const float4*)(vg + (size_t)i * 4);
    }
    __syncthreads();

    const float* qg = g_q + (size_t)bh * LTOK * HEADD;

    for (int q0 = 0; q0 < LTOK; q0 += 64) {
        const int qn = min(64, LTOK - q0);
        const int qglob = q0 + qt;

        float4 Q[8];
        {
            const float* qrow = qg + (size_t)min(qglob, LTOK - 1) * HEADD;
            #pragma unroll
            for (int c = 0; c < 8; c++) Q[c] = *(const float4*)(qrow + c * 4);
        }

        float mloc = -1e30f;
        for (int kj = k0r; kj < k1r; kj++) {
            const float* krow = Ks + kj * 36;
            float p0 = 0.f, p1 = 0.f, p2 = 0.f, p3 = 0.f;
            #pragma unroll
            for (int c = 0; c < 2; c++) {
                float4 k0 = *(const float4*)(krow + (c * 4 + 0) * 4);
                float4 k1 = *(const float4*)(krow + (c * 4 + 1) * 4);
                float4 k2 = *(const float4*)(krow + (c * 4 + 2) * 4);
                float4 k3 = *(const float4*)(krow + (c * 4 + 3) * 4);
                float4 q0v = Q[c * 4 + 0], q1v = Q[c * 4 + 1];
                float4 q2v = Q[c * 4 + 2], q3v = Q[c * 4 + 3];
                p0 = fmaf(q0v.x, k0.x, fmaf(q0v.y, k0.y,
                     fmaf(q0v.z, k0.z, fmaf(q0v.w, k0.w, p0))));
                p1 = fmaf(q1v.x, k1.x, fmaf(q1v.y, k1.y,
                     fmaf(q1v.z, k1.z, fmaf(q1v.w, k1.w, p1))));
                p2 = fmaf(q2v.x, k2.x, fmaf(q2v.y, k2.y,
                     fmaf(q2v.z, k2.z, fmaf(q2v.w, k2.w, p2))));
                p3 = fmaf(q3v.x, k3.x, fmaf(q3v.y, k3.y,
                     fmaf(q3v.z, k3.z, fmaf(q3v.w, k3.w, p3))));
            }
            float dot = (p0 + p1) + (p2 + p3);
            size_t off = (size_t)kj * LTOK + qglob;
            float s = mT[off] ? -1e30f : fmaf(dot, QSCALE, bias_h[off]);
            mloc = fmaxf(mloc, s);
            SsT[kj * 64 + qt] = s;
        }
        Red[r * 64 + qt] = mloc;
        __syncthreads();

        if (tid < 64) {
            float m = Red[tid];
            #pragma unroll
            for (int rr = 1; rr < 8; rr++) m = fmaxf(m, Red[rr * 64 + tid]);
            Mf[tid] = m;
        }
        __syncthreads();

        {
            float mq = Mf[qt];
            float ssum = 0.f;
            for (int kj = k0r; kj < k1r; kj++) {
                float p = __expf(SsT[kj * 64 + qt] - mq);
                SsT[kj * 64 + qt] = p;
                ssum += p;
            }
            Red[r * 64 + qt] = ssum;
        }
        __syncthreads();

        if (tid < 64) {
            float s = Red[tid];
            #pragma unroll
            for (int rr = 1; rr < 8; rr++) s += Red[rr * 64 + tid];
            Sf[tid] = 1.f / s;
        }
        __syncthreads();

        if (tid < 128) {
            int qgp = tid >> 3;
            int cg  = tid & 7;
            float4 a0 = make_float4(0.f, 0.f, 0.f, 0.f);
            float4 a1 = make_float4(0.f, 0.f, 0.f, 0.f);
            float4 a2 = make_float4(0.f, 0.f, 0.f, 0.f);
            float4 a3 = make_float4(0.f, 0.f, 0.f, 0.f);
            const float* sp = SsT + qgp * 4;
            const float* vp = Vs + cg * 4;
            #pragma unroll 4
            for (int j = 0; j < LTOK; j++) {
                float4 pv = *(const float4*)(sp + j * 64);
                float4 vv = *(const float4*)(vp + j * 36);
                a0.x = fmaf(pv.x, vv.x, a0.x);
                a0.y = fmaf(pv.x, vv.y, a0.y);
                a0.z = fmaf(pv.x, vv.z, a0.z);
                a0.w = fmaf(pv.x, vv.w, a0.w);
                a1.x = fmaf(pv.y, vv.x, a1.x);
                a1.y = fmaf(pv.y, vv.y, a1.y);
                a1.z = fmaf(pv.y, vv.z, a1.z);
                a1.w = fmaf(pv.y, vv.w, a1.w);
                a2.x = fmaf(pv.z, vv.x, a2.x);
                a2.y = fmaf(pv.z, vv.y, a2.y);
                a2.z = fmaf(pv.z, vv.z, a2.z);
                a2.w = fmaf(pv.z, vv.w, a2.w);
                a3.x = fmaf(pv.w, vv.x, a3.x);
                a3.y = fmaf(pv.w, vv.y, a3.y);
                a3.z = fmaf(pv.w, vv.z, a3.z);
                a3.w = fmaf(pv.w, vv.w, a3.w);
            }
            float4 accs[4] = {a0, a1, a2, a3};
            #pragma unroll
            for (int i = 0; i < 4; i++) {
                int qi = qgp * 4 + i;
                if (qi < qn) {
                    float inv = Sf[qi];
                    float4 o = make_float4(accs[i].x * inv, accs[i].y * inv,
                                           accs[i].z * inv, accs[i].w * inv);
                    float* og = g_ao + ((size_t)(n * LTOK + q0 + qi)) * DIMM
                                + h * HEADD + cg * 4;
                    *(float4*)og = o;
                }
            }
        }
        __syncthreads();
    }
}

// ======================================================================
extern "C" void kernel_launch(void* const* d_in, const int* in_sizes, int n_in,
                              void* d_out, int out_size)
{
    const float *x = nullptr, *qkvw = nullptr, *tbl = nullptr;
    const float *pw = nullptr, *pb = nullptr;
    const void* mask = nullptr;
    const int* ridx = nullptr;
    for (int i = 0; i < n_in; i++) {
        switch (in_sizes[i]) {
            case 8429568:  x    = (const float*)d_in[i]; break;
            case 442368:   qkvw = (const float*)d_in[i]; break;
            case 26364:    tbl  = (const float*)d_in[i]; break;
            case 147456:   pw   = (const float*)d_in[i]; break;
            case 384:      pb   = (const float*)d_in[i]; break;
            case 7530496:  mask = d_in[i]; break;
            case 117649:   ridx = (const int*)d_in[i]; break;
        }
    }
    if (n_in >= 7) {
        if (!x)    x    = (const float*)d_in[0];
        if (!qkvw) qkvw = (const float*)d_in[1];
        if (!tbl)  tbl  = (const float*)d_in[2];
        if (!pw)   pw   = (const float*)d_in[3];
        if (!pb)   pb   = (const float*)d_in[4];
        if (!mask) mask = d_in[5];
        if (!ridx) ridx = (const int*)d_in[6];
    }

    // 0) prep: mask dtype, transposed bias / mask
    detect_mask_kernel<<<1, 256>>>((const unsigned int*)mask);
    int nb = (L2TOK + 255) / 256;
    biast_prep_kernel<<<nb, 256>>>(tbl, ridx);
    maskt_prep_kernel<<<dim3(nb, NWIN), 256>>>(mask);

    // 1) QKV projection (tf32 tensor cores) + scatter to [n][h][l][c]
    mm_tf32_kernel<<<dim3(172, 18), 256>>>(x, qkvw, MROWS, 3 * DIMM, DIMM, 1,
                                           nullptr, nullptr);

    // 2) fused attention
    size_t smem = (size_t)(LTOK * 36 * 2 + LTOK * 64 + 8 * 64 + 128)
                  * sizeof(float);
    cudaFuncSetAttribute(attn_kernel,
                         cudaFuncAttributeMaxDynamicSharedMemorySize, (int)smem);
    attn_kernel<<<NWIN * NHEAD, 512, smem>>>();

    // 3) output projection (tf32 tensor cores) + bias
    mm_tf32_kernel<<<dim3(172, 6), 256>>>(nullptr, pw, MROWS, DIMM, DIMM, 0,
                                          (float*)d_out, pb);
}